// round 6
// baseline (speedup 1.0000x reference)
#include <cuda_runtime.h>
#include <cuda_fp16.h>
#include <cstdint>

// ---------------------------------------------------------------------------
// Problem constants
// ---------------------------------------------------------------------------
static constexpr int B_  = 8;
static constexpr int C_  = 256;
static constexpr int NL_ = 4;
static constexpr int NP_ = 4;
static constexpr int NLAYERS_ = 6;
static constexpr int FFN_ = 1024;
static constexpr int DH_ = 32;
static constexpr int Q_  = 64*64 + 32*32 + 16*16 + 8*8;   // 5440
static constexpr int M_  = B_ * Q_;                        // 43520

// per-layer weight offsets inside the split-weight pool ([N][K] layout)
static constexpr size_t OFF_WV  = 0;
static constexpr size_t OFF_WSA = 65536;    // fused [Wsamp(256) ; Wattn(128)]
static constexpr size_t OFF_WO  = 163840;
static constexpr size_t OFF_W1  = 229376;
static constexpr size_t OFF_W2  = 491520;
static constexpr size_t W_LAYER = 753664;

__device__ __constant__ int c_lvl_h[4]     = {64, 32, 16, 8};
__device__ __constant__ int c_lvl_w[4]     = {64, 32, 16, 8};
__device__ __constant__ int c_lvl_start[4] = {0, 4096, 5120, 5376};

// ---------------------------------------------------------------------------
// Scratch (static device globals)
// ---------------------------------------------------------------------------
__device__ float  d_pos    [(size_t)M_ * C_];
__device__ float  d_value  [(size_t)M_ * C_];
__device__ float  d_offlog [(size_t)M_ * 384];    // fused offsets(256)+logits(128)
__device__ float  d_ref    [Q_ * 2];
__device__ float  d_bsa    [NLAYERS_ * 384];      // fused bias [bsamp ; battn]
__device__ __half d_xh[(size_t)M_ * C_],   d_xl[(size_t)M_ * C_];
__device__ __half d_qh[(size_t)M_ * C_],   d_ql[(size_t)M_ * C_];
__device__ __half d_ah[(size_t)M_ * C_],   d_al[(size_t)M_ * C_];
__device__ __half d_hh[(size_t)M_ * FFN_], d_hl[(size_t)M_ * FFN_];
__device__ __half d_wh[(size_t)NLAYERS_ * W_LAYER], d_wl[(size_t)NLAYERS_ * W_LAYER];

// ---------------------------------------------------------------------------
// Helpers
// ---------------------------------------------------------------------------
__device__ __forceinline__ uint32_t smem_u32(const void* p) {
    uint32_t a;
    asm("{ .reg .u64 t; cvta.to.shared.u64 t, %1; cvt.u32.u64 %0, t; }"
        : "=r"(a) : "l"(p));
    return a;
}
#define CP16(dst, src) \
    asm volatile("cp.async.cg.shared.global [%0], [%1], 16;" :: "r"(dst), "l"(src))
#define CP_COMMIT() asm volatile("cp.async.commit_group;" ::: "memory")
#define CP_WAIT(n)  asm volatile("cp.async.wait_group %0;" :: "n"(n) : "memory")

__device__ __forceinline__ void ldsm4(uint32_t& r0, uint32_t& r1,
                                      uint32_t& r2, uint32_t& r3, uint32_t addr)
{
    asm volatile("ldmatrix.sync.aligned.m8n8.x4.shared.b16 {%0,%1,%2,%3}, [%4];"
                 : "=r"(r0), "=r"(r1), "=r"(r2), "=r"(r3) : "r"(addr));
}
__device__ __forceinline__ void mma16816(float* c, const uint32_t* a,
                                         const uint32_t* b)
{
    asm volatile(
        "mma.sync.aligned.m16n8k16.row.col.f32.f16.f16.f32 "
        "{%0,%1,%2,%3}, {%4,%5,%6,%7}, {%8,%9}, {%0,%1,%2,%3};\n"
        : "+f"(c[0]), "+f"(c[1]), "+f"(c[2]), "+f"(c[3])
        : "r"(a[0]), "r"(a[1]), "r"(a[2]), "r"(a[3]), "r"(b[0]), "r"(b[1]));
}

struct alignas(8) H4 { __half2 a, b; };
__device__ __forceinline__ void split2(float v, __half& h, __half& l)
{
    h = __float2half_rn(v);
    l = __float2half_rn(v - __half2float(h));
}

// ---------------------------------------------------------------------------
// Setup kernels
// ---------------------------------------------------------------------------
__global__ void ref_kernel()
{
    int q = blockIdx.x * blockDim.x + threadIdx.x;
    if (q >= Q_) return;
    int lvl = (q < 4096) ? 0 : (q < 5120) ? 1 : (q < 5376) ? 2 : 3;
    int start = c_lvl_start[lvl];
    int w = c_lvl_w[lvl], h = c_lvl_h[lvl];
    int idx = q - start;
    int row = idx / w, col = idx - row * w;
    d_ref[q * 2 + 0] = (col + 0.5f) / (float)w;
    d_ref[q * 2 + 1] = (row + 0.5f) / (float)h;
}

__global__ void bias_pack_kernel(const float* __restrict__ bsamp,
                                 const float* __restrict__ battn)
{
    int i = blockIdx.x * blockDim.x + threadIdx.x;
    if (i >= NLAYERS_ * 384) return;
    int layer = i / 384, j = i % 384;
    d_bsa[i] = (j < 256) ? bsamp[layer * 256 + j] : battn[layer * 128 + (j - 256)];
}

// pos = pos_flat + lvl_emb; x = src; (xh,xl)=split(src); (qh,ql)=split(src+pos)
__global__ void init_kernel(const float* __restrict__ src,
                            const float* __restrict__ pos_flat,
                            const float* __restrict__ level_embed,
                            float* __restrict__ x)
{
    size_t idx = (size_t)blockIdx.x * blockDim.x + threadIdx.x;
    if (idx >= (size_t)M_ * C_) return;
    int c = idx & (C_ - 1);
    int q = (int)((idx >> 8) % Q_);
    int lvl = (q < 4096) ? 0 : (q < 5120) ? 1 : (q < 5376) ? 2 : 3;
    float p = pos_flat[idx] + level_embed[lvl * C_ + c];
    d_pos[idx] = p;
    float v = src[idx];
    x[idx] = v;
    __half h, l;
    split2(v, h, l);     d_xh[idx] = h; d_xl[idx] = l;
    split2(v + p, h, l); d_qh[idx] = h; d_ql[idx] = l;
}

// weight split+transpose:  W (K,N) fp32 -> Wt[N][K] hi/lo halves
__global__ void wsplit_kernel(const float* __restrict__ Wval,
                              const float* __restrict__ Wsamp,
                              const float* __restrict__ Wattn,
                              const float* __restrict__ Wout,
                              const float* __restrict__ Wfc1,
                              const float* __restrict__ Wfc2)
{
    int bz = blockIdx.z;
    int layer = bz / 6, mat = bz % 6;
    const float* src; int K, N; size_t doff;
    switch (mat) {
        case 0: src = Wval  + (size_t)layer * 65536;  K = 256;  N = 256;  doff = OFF_WV; break;
        case 1: src = Wsamp + (size_t)layer * 65536;  K = 256;  N = 256;  doff = OFF_WSA; break;
        case 2: src = Wattn + (size_t)layer * 32768;  K = 256;  N = 128;  doff = OFF_WSA + 65536; break;
        case 3: src = Wout  + (size_t)layer * 65536;  K = 256;  N = 256;  doff = OFF_WO; break;
        case 4: src = Wfc1  + (size_t)layer * 262144; K = 256;  N = 1024; doff = OFF_W1; break;
        default:src = Wfc2  + (size_t)layer * 262144; K = 1024; N = 256;  doff = OFF_W2; break;
    }
    doff += (size_t)layer * W_LAYER;
    int bx = blockIdx.x, by = blockIdx.y;
    if (bx * 32 >= N || by * 32 >= K) return;

    __shared__ float tile[32][33];
    int tx = threadIdx.x, ty = threadIdx.y;   // 32 x 8
#pragma unroll
    for (int i = 0; i < 4; i++) {
        int k = by * 32 + ty + i * 8;
        tile[ty + i * 8][tx] = src[(size_t)k * N + bx * 32 + tx];
    }
    __syncthreads();
#pragma unroll
    for (int i = 0; i < 4; i++) {
        int n = bx * 32 + ty + i * 8;
        int k = by * 32 + tx;
        __half h, l;
        split2(tile[tx][ty + i * 8], h, l);
        d_wh[doff + (size_t)n * K + k] = h;
        d_wl[doff + (size_t)n * K + k] = l;
    }
}

// ---------------------------------------------------------------------------
// Split-fp16 x3 tensor GEMM, 3-stage cp.async pipeline, XOR-swizzled smem.
// Tile 128x128x32. 256 thr = 8 warps (2M x 4N), warp tile 64x32.
// ---------------------------------------------------------------------------
static constexpr int ARR = 8192;
static constexpr int STG = 32768;

__device__ __forceinline__ void load_stage(uint32_t base,
    const __half* __restrict__ A0, const __half* __restrict__ A1,
    const __half* __restrict__ B0, const __half* __restrict__ B1,
    int bm, int bn, int K, int kt, int tid)
{
#pragma unroll
    for (int it = 0; it < 8; it++) {
        int i   = it * 256 + tid;
        int arr = i >> 9;
        int rem = i & 511;
        int r   = rem >> 2;
        int c   = rem & 3;
        const __half* g;
        if      (arr == 0) g = A0 + (size_t)(bm + r) * K + kt;
        else if (arr == 1) g = A1 + (size_t)(bm + r) * K + kt;
        else if (arr == 2) g = B0 + (size_t)(bn + r) * K + kt;
        else               g = B1 + (size_t)(bn + r) * K + kt;
        uint32_t dst = base + arr * ARR + r * 64 + ((c ^ ((r >> 1) & 3)) << 4);
        CP16(dst, (const char*)g + c * 16);
    }
}

template<bool RELU, bool OUTF32, bool OUTSPLIT>
__global__ __launch_bounds__(256, 2)
void hgemm_kernel(const __half* __restrict__ Ahg, const __half* __restrict__ Alg,
                  const __half* __restrict__ Bhg, const __half* __restrict__ Blg,
                  const float* __restrict__ bias,
                  float* __restrict__ Cf, __half* __restrict__ Ch,
                  __half* __restrict__ Cl, int M, int N, int K)
{
    extern __shared__ char smem[];
    const uint32_t sb = smem_u32(smem);
    const int tid  = threadIdx.x;
    const int warp = tid >> 5, lane = tid & 31;
    const int bm = blockIdx.y * 128, bn = blockIdx.x * 128;
    const int wm = (warp >> 2) * 64;
    const int wn = (warp & 3) * 32;

    float acc[4][4][4];
#pragma unroll
    for (int i = 0; i < 4; i++)
#pragma unroll
        for (int j = 0; j < 4; j++)
#pragma unroll
            for (int r = 0; r < 4; r++) acc[i][j][r] = 0.f;

    const int a_row = (lane & 7) + ((lane >> 3) & 1) * 8;
    const int a_ch  = (lane >> 4) & 1;
    const int b_row = (lane & 7) + ((lane >> 4) & 1) * 8;
    const int b_ch  = (lane >> 3) & 1;

    const int T = K >> 5;

    load_stage(sb,       Ahg, Alg, Bhg, Blg, bm, bn, K, 0,  tid);
    CP_COMMIT();
    load_stage(sb + STG, Ahg, Alg, Bhg, Blg, bm, bn, K, 32, tid);
    CP_COMMIT();

    uint32_t st = sb;
    for (int t = 0; t < T; t++) {
        CP_WAIT(1);
        __syncthreads();

        if (t + 2 < T) {
            uint32_t nxt = sb + (uint32_t)((t + 2) % 3) * STG;
            load_stage(nxt, Ahg, Alg, Bhg, Blg, bm, bn, K, (t + 2) * 32, tid);
        }
        CP_COMMIT();

#pragma unroll
        for (int ks = 0; ks < 2; ks++) {
            const int cb = ks * 2;
            uint32_t bh[4][2], bl[4][2];
#pragma unroll
            for (int np = 0; np < 2; np++) {
                int r = wn + np * 16 + b_row;
                uint32_t addr = st + 2 * ARR + r * 64 +
                    (uint32_t)(((cb + b_ch) ^ ((r >> 1) & 3)) << 4);
                ldsm4(bh[2*np][0], bh[2*np][1], bh[2*np+1][0], bh[2*np+1][1], addr);
                ldsm4(bl[2*np][0], bl[2*np][1], bl[2*np+1][0], bl[2*np+1][1],
                      addr + ARR);
            }
#pragma unroll
            for (int mt = 0; mt < 4; mt++) {
                int r = wm + mt * 16 + a_row;
                uint32_t addr = st + r * 64 +
                    (uint32_t)(((cb + a_ch) ^ ((r >> 1) & 3)) << 4);
                uint32_t aH[4], aL[4];
                ldsm4(aH[0], aH[1], aH[2], aH[3], addr);
                ldsm4(aL[0], aL[1], aL[2], aL[3], addr + ARR);
#pragma unroll
                for (int nt = 0; nt < 4; nt++) {
                    mma16816(acc[mt][nt], aH, bh[nt]);
                    mma16816(acc[mt][nt], aH, bl[nt]);
                    mma16816(acc[mt][nt], aL, bh[nt]);
                }
            }
        }
        st = sb + (uint32_t)((t + 1) % 3) * STG;
    }

    const int g  = lane >> 2;
    const int tq = lane & 3;
#pragma unroll
    for (int mt = 0; mt < 4; mt++) {
        const int r0 = bm + wm + mt * 16 + g;
#pragma unroll
        for (int nt = 0; nt < 4; nt++) {
            const int c0 = bn + wn + nt * 8 + tq * 2;
            float2 bv = *(const float2*)&bias[c0];
            float o0 = acc[mt][nt][0] + bv.x;
            float o1 = acc[mt][nt][1] + bv.y;
            float o2 = acc[mt][nt][2] + bv.x;
            float o3 = acc[mt][nt][3] + bv.y;
            if (RELU) {
                o0 = fmaxf(o0, 0.f); o1 = fmaxf(o1, 0.f);
                o2 = fmaxf(o2, 0.f); o3 = fmaxf(o3, 0.f);
            }
            if (OUTF32) {
                *(float2*)&Cf[(size_t)r0 * N + c0]       = make_float2(o0, o1);
                *(float2*)&Cf[(size_t)(r0 + 8) * N + c0] = make_float2(o2, o3);
            }
            if (OUTSPLIT) {
                __half h0,h1,h2,h3,l0,l1,l2,l3;
                split2(o0,h0,l0); split2(o1,h1,l1);
                split2(o2,h2,l2); split2(o3,h3,l3);
                *(__half2*)&Ch[(size_t)r0 * N + c0]       = __halves2half2(h0,h1);
                *(__half2*)&Cl[(size_t)r0 * N + c0]       = __halves2half2(l0,l1);
                *(__half2*)&Ch[(size_t)(r0 + 8) * N + c0] = __halves2half2(h2,h3);
                *(__half2*)&Cl[(size_t)(r0 + 8) * N + c0] = __halves2half2(l2,l3);
            }
        }
    }
}

// ---------------------------------------------------------------------------
// Fused GEMM + residual + LayerNorm.  Tile 128M x 256N (full row per CTA),
// 512 thr = 16 warps (2M x 8N), warp tile 64x32, 3-stage cp.async.
//   x <- LN( x + A @ B^T + bias ) * gamma + beta ; writes x, xh/xl [,qh/ql].
// Stage: Ah(8K) Al(8K) Bh(16K) Bl(16K) = 48K; 3 stages = 147456 B.
// ---------------------------------------------------------------------------
static constexpr int STG2 = 49152;

__device__ __forceinline__ void load_stage2(uint32_t base,
    const __half* __restrict__ A0, const __half* __restrict__ A1,
    const __half* __restrict__ B0, const __half* __restrict__ B1,
    int bm, int K, int kt, int tid)
{
    {
        int r = tid >> 2, c = tid & 3;
        uint32_t sw = (uint32_t)((c ^ ((r >> 1) & 3)) << 4);
        CP16(base + r * 64 + sw,
             (const char*)(A0 + (size_t)(bm + r) * K + kt) + c * 16);
        CP16(base + 8192 + r * 64 + sw,
             (const char*)(A1 + (size_t)(bm + r) * K + kt) + c * 16);
    }
#pragma unroll
    for (int it = 0; it < 2; it++) {
        int i = it * 512 + tid;
        int r = i >> 2, c = i & 3;
        uint32_t sw = (uint32_t)((c ^ ((r >> 1) & 3)) << 4);
        CP16(base + 16384 + r * 64 + sw,
             (const char*)(B0 + (size_t)r * K + kt) + c * 16);
        CP16(base + 32768 + r * 64 + sw,
             (const char*)(B1 + (size_t)r * K + kt) + c * 16);
    }
}

template<bool WRITE_Q>
__global__ __launch_bounds__(512, 1)
void hgemm_ln_kernel(const __half* __restrict__ Ahg, const __half* __restrict__ Alg,
                     const __half* __restrict__ Bhg, const __half* __restrict__ Blg,
                     const float* __restrict__ bias,
                     const float* __restrict__ gam, const float* __restrict__ bet,
                     float* __restrict__ x, int K)
{
    extern __shared__ char smem[];
    const uint32_t sb = smem_u32(smem);
    const int tid  = threadIdx.x;
    const int warp = tid >> 5, lane = tid & 31;
    const int bm = blockIdx.y * 128;
    const int wmL = (warp >> 3) * 64;     // local warp row base (0/64)
    const int wn  = (warp & 7) * 32;      // warp col base

    float acc[4][4][4];
#pragma unroll
    for (int i = 0; i < 4; i++)
#pragma unroll
        for (int j = 0; j < 4; j++)
#pragma unroll
            for (int r = 0; r < 4; r++) acc[i][j][r] = 0.f;

    const int a_row = (lane & 7) + ((lane >> 3) & 1) * 8;
    const int a_ch  = (lane >> 4) & 1;
    const int b_row = (lane & 7) + ((lane >> 4) & 1) * 8;
    const int b_ch  = (lane >> 3) & 1;

    const int T = K >> 5;

    load_stage2(sb,        Ahg, Alg, Bhg, Blg, bm, K, 0,  tid);
    CP_COMMIT();
    load_stage2(sb + STG2, Ahg, Alg, Bhg, Blg, bm, K, 32, tid);
    CP_COMMIT();

    uint32_t st = sb;
    for (int t = 0; t < T; t++) {
        CP_WAIT(1);
        __syncthreads();

        if (t + 2 < T) {
            uint32_t nxt = sb + (uint32_t)((t + 2) % 3) * STG2;
            load_stage2(nxt, Ahg, Alg, Bhg, Blg, bm, K, (t + 2) * 32, tid);
        }
        CP_COMMIT();

#pragma unroll
        for (int ks = 0; ks < 2; ks++) {
            const int cb = ks * 2;
            uint32_t bh[4][2], bl[4][2];
#pragma unroll
            for (int np = 0; np < 2; np++) {
                int r = wn + np * 16 + b_row;
                uint32_t addr = st + 16384 + r * 64 +
                    (uint32_t)(((cb + b_ch) ^ ((r >> 1) & 3)) << 4);
                ldsm4(bh[2*np][0], bh[2*np][1], bh[2*np+1][0], bh[2*np+1][1], addr);
                ldsm4(bl[2*np][0], bl[2*np][1], bl[2*np+1][0], bl[2*np+1][1],
                      addr + 16384);
            }
#pragma unroll
            for (int mt = 0; mt < 4; mt++) {
                int r = wmL + mt * 16 + a_row;
                uint32_t addr = st + r * 64 +
                    (uint32_t)(((cb + a_ch) ^ ((r >> 1) & 3)) << 4);
                uint32_t aH[4], aL[4];
                ldsm4(aH[0], aH[1], aH[2], aH[3], addr);
                ldsm4(aL[0], aL[1], aL[2], aL[3], addr + 8192);
#pragma unroll
                for (int nt = 0; nt < 4; nt++) {
                    mma16816(acc[mt][nt], aH, bh[nt]);
                    mma16816(acc[mt][nt], aH, bl[nt]);
                    mma16816(acc[mt][nt], aL, bh[nt]);
                }
            }
        }
        st = sb + (uint32_t)((t + 1) % 3) * STG2;
    }

    // ---- epilogue: v = acc + bias + resid ----
    const int g  = lane >> 2;
    const int tq = lane & 3;
#pragma unroll
    for (int mt = 0; mt < 4; mt++) {
        const int r0 = bm + wmL + mt * 16 + g;
#pragma unroll
        for (int nt = 0; nt < 4; nt++) {
            const int c0 = wn + nt * 8 + tq * 2;
            float2 bv = *(const float2*)&bias[c0];
            float2 x0 = *(const float2*)&x[(size_t)r0 * 256 + c0];
            float2 x1 = *(const float2*)&x[(size_t)(r0 + 8) * 256 + c0];
            acc[mt][nt][0] += bv.x + x0.x;
            acc[mt][nt][1] += bv.y + x0.y;
            acc[mt][nt][2] += bv.x + x1.x;
            acc[mt][nt][3] += bv.y + x1.y;
        }
    }

    // ---- LN stats: per-row sums across the block ----
    __syncthreads();                       // all smem stage reads finished
    float* sred = (float*)smem;            // [8 warpcols][128 rows][2]
#pragma unroll
    for (int mt = 0; mt < 4; mt++) {
#pragma unroll
        for (int hf = 0; hf < 2; hf++) {
            float s1 = 0.f, s2 = 0.f;
#pragma unroll
            for (int nt = 0; nt < 4; nt++) {
                float a = acc[mt][nt][2 * hf + 0];
                float b = acc[mt][nt][2 * hf + 1];
                s1 += a + b;
                s2 += a * a + b * b;
            }
            s1 += __shfl_xor_sync(0xFFFFFFFFu, s1, 1);
            s1 += __shfl_xor_sync(0xFFFFFFFFu, s1, 2);
            s2 += __shfl_xor_sync(0xFFFFFFFFu, s2, 1);
            s2 += __shfl_xor_sync(0xFFFFFFFFu, s2, 2);
            if (tq == 0) {
                int rl = wmL + mt * 16 + g + 8 * hf;
                sred[((warp & 7) * 128 + rl) * 2 + 0] = s1;
                sred[((warp & 7) * 128 + rl) * 2 + 1] = s2;
            }
        }
    }
    __syncthreads();
    float* smean = (float*)(smem + 32768);
    float* srstd = smean + 128;
    if (tid < 128) {
        float s1 = 0.f, s2 = 0.f;
#pragma unroll
        for (int w = 0; w < 8; w++) {
            s1 += sred[(w * 128 + tid) * 2 + 0];
            s2 += sred[(w * 128 + tid) * 2 + 1];
        }
        float mean = s1 * (1.f / 256.f);
        float var  = s2 * (1.f / 256.f) - mean * mean;
        smean[tid] = mean;
        srstd[tid] = rsqrtf(var + 1e-5f);
    }
    __syncthreads();

    // ---- normalize + write ----
#pragma unroll
    for (int mt = 0; mt < 4; mt++) {
        const int rl0 = wmL + mt * 16 + g;
        const int r0  = bm + rl0;
        const float m0 = smean[rl0],     rs0 = srstd[rl0];
        const float m1 = smean[rl0 + 8], rs1 = srstd[rl0 + 8];
#pragma unroll
        for (int nt = 0; nt < 4; nt++) {
            const int c0 = wn + nt * 8 + tq * 2;
            float2 gg = *(const float2*)&gam[c0];
            float2 bb = *(const float2*)&bet[c0];
            float o0 = (acc[mt][nt][0] - m0) * rs0 * gg.x + bb.x;
            float o1 = (acc[mt][nt][1] - m0) * rs0 * gg.y + bb.y;
            float o2 = (acc[mt][nt][2] - m1) * rs1 * gg.x + bb.x;
            float o3 = (acc[mt][nt][3] - m1) * rs1 * gg.y + bb.y;
            const size_t i0 = (size_t)r0 * 256 + c0;
            const size_t i1 = (size_t)(r0 + 8) * 256 + c0;
            *(float2*)&x[i0] = make_float2(o0, o1);
            *(float2*)&x[i1] = make_float2(o2, o3);
            __half h0,h1,h2,h3,l0,l1,l2,l3;
            split2(o0,h0,l0); split2(o1,h1,l1);
            split2(o2,h2,l2); split2(o3,h3,l3);
            *(__half2*)&d_xh[i0] = __halves2half2(h0,h1);
            *(__half2*)&d_xl[i0] = __halves2half2(l0,l1);
            *(__half2*)&d_xh[i1] = __halves2half2(h2,h3);
            *(__half2*)&d_xl[i1] = __halves2half2(l2,l3);
            if (WRITE_Q) {
                float2 p0 = *(const float2*)&d_pos[i0];
                float2 p1 = *(const float2*)&d_pos[i1];
                split2(o0 + p0.x, h0, l0); split2(o1 + p0.y, h1, l1);
                split2(o2 + p1.x, h2, l2); split2(o3 + p1.y, h3, l3);
                *(__half2*)&d_qh[i0] = __halves2half2(h0,h1);
                *(__half2*)&d_ql[i0] = __halves2half2(l0,l1);
                *(__half2*)&d_qh[i1] = __halves2half2(h2,h3);
                *(__half2*)&d_ql[i1] = __halves2half2(l2,l3);
            }
        }
    }
}

// ---------------------------------------------------------------------------
// Deformable attention sampling -> split-half output (feeds out-proj GEMM)
// ---------------------------------------------------------------------------
__global__ __launch_bounds__(256)
void deform_kernel(const float* __restrict__ value,
                   const float* __restrict__ offlog)
{
    const int bq   = blockIdx.x;
    const int q    = bq % Q_;
    const int b    = bq / Q_;
    const int h    = threadIdx.x >> 5;
    const int lane = threadIdx.x & 31;
    const unsigned FULL = 0xFFFFFFFFu;

    float logit = offlog[(size_t)bq * 384 + 256 + h * 16 + (lane & 15)];
    float mx = logit;
#pragma unroll
    for (int s = 8; s; s >>= 1) mx = fmaxf(mx, __shfl_xor_sync(FULL, mx, s));
    float e = expf(logit - mx);
    float sm = e;
#pragma unroll
    for (int s = 8; s; s >>= 1) sm += __shfl_xor_sync(FULL, sm, s);
    float aw = e / sm;

    float offv = offlog[(size_t)bq * 384 + h * 32 + lane];
    const float rx = d_ref[q * 2 + 0];
    const float ry = d_ref[q * 2 + 1];

    float acc = 0.f;
    const float* vb = value + (size_t)b * Q_ * C_ + h * DH_ + lane;

#pragma unroll
    for (int l = 0; l < NL_; l++) {
        const int   W  = c_lvl_w[l], H = c_lvl_h[l], st = c_lvl_start[l];
        const float fw = (float)W, fh = (float)H;
        const float iw = 1.f / fw, ih = 1.f / fh;
#pragma unroll
        for (int p = 0; p < NP_; p++) {
            const int j = l * NP_ + p;
            float ox  = __shfl_sync(FULL, offv, 2 * j);
            float oy  = __shfl_sync(FULL, offv, 2 * j + 1);
            float wj  = __shfl_sync(FULL, aw,   j);

            float x = (rx + ox * iw) * fw - 0.5f;
            float y = (ry + oy * ih) * fh - 0.5f;
            float x0f = floorf(x), y0f = floorf(y);
            int   x0  = (int)x0f,  y0  = (int)y0f;
            float fx = x - x0f, fy = y - y0f;
            float s = 0.f;

            bool vx0 = (x0 >= 0)     && (x0 < W);
            bool vx1 = (x0 + 1 >= 0) && (x0 + 1 < W);
            if (y0 >= 0 && y0 < H) {
                const float* rp = vb + (size_t)(st + y0 * W) * C_;
                float wy = 1.f - fy;
                if (vx0) s += wy * (1.f - fx) * rp[(size_t)x0 * C_];
                if (vx1) s += wy * fx         * rp[(size_t)(x0 + 1) * C_];
            }
            if (y0 + 1 >= 0 && y0 + 1 < H) {
                const float* rp = vb + (size_t)(st + (y0 + 1) * W) * C_;
                if (vx0) s += fy * (1.f - fx) * rp[(size_t)x0 * C_];
                if (vx1) s += fy * fx         * rp[(size_t)(x0 + 1) * C_];
            }
            acc = fmaf(wj, s, acc);
        }
    }
    __half hh, hl;
    split2(acc, hh, hl);
    const size_t oidx = (size_t)bq * C_ + h * DH_ + lane;
    d_ah[oidx] = hh;
    d_al[oidx] = hl;
}

// ---------------------------------------------------------------------------
// Launch
// ---------------------------------------------------------------------------
extern "C" void kernel_launch(void* const* d_in, const int* in_sizes, int n_in,
                              void* d_out, int out_size)
{
    const float* src   = (const float*)d_in[0];
    const float* posf  = (const float*)d_in[1];
    const float* lemb  = (const float*)d_in[2];
    const float* Wsamp = (const float*)d_in[3];
    const float* bsamp = (const float*)d_in[4];
    const float* Wattn = (const float*)d_in[5];
    const float* battn = (const float*)d_in[6];
    const float* Wval  = (const float*)d_in[7];
    const float* bval  = (const float*)d_in[8];
    const float* Wout  = (const float*)d_in[9];
    const float* bout  = (const float*)d_in[10];
    const float* g1    = (const float*)d_in[11];
    const float* b1    = (const float*)d_in[12];
    const float* Wfc1  = (const float*)d_in[13];
    const float* bfc1  = (const float*)d_in[14];
    const float* Wfc2  = (const float*)d_in[15];
    const float* bfc2  = (const float*)d_in[16];
    const float* g2    = (const float*)d_in[17];
    const float* b2    = (const float*)d_in[18];

    float* x = (float*)d_out;

    static const int SMEM_DYN  = 98304;    // 3 x 32768
    static const int SMEM_DYN2 = 147456;   // 3 x 49152
    cudaFuncSetAttribute(hgemm_kernel<false, true,  false>,
                         cudaFuncAttributeMaxDynamicSharedMemorySize, SMEM_DYN);
    cudaFuncSetAttribute(hgemm_kernel<true,  false, true>,
                         cudaFuncAttributeMaxDynamicSharedMemorySize, SMEM_DYN);
    cudaFuncSetAttribute(hgemm_ln_kernel<false>,
                         cudaFuncAttributeMaxDynamicSharedMemorySize, SMEM_DYN2);
    cudaFuncSetAttribute(hgemm_ln_kernel<true>,
                         cudaFuncAttributeMaxDynamicSharedMemorySize, SMEM_DYN2);

    float *p_val, *p_ol, *p_bsa;
    __half *p_xh, *p_xl, *p_qh, *p_ql, *p_ah, *p_al, *p_hh, *p_hl, *p_wh, *p_wl;
    cudaGetSymbolAddress((void**)&p_val, d_value);
    cudaGetSymbolAddress((void**)&p_ol,  d_offlog);
    cudaGetSymbolAddress((void**)&p_bsa, d_bsa);
    cudaGetSymbolAddress((void**)&p_xh, d_xh);
    cudaGetSymbolAddress((void**)&p_xl, d_xl);
    cudaGetSymbolAddress((void**)&p_qh, d_qh);
    cudaGetSymbolAddress((void**)&p_ql, d_ql);
    cudaGetSymbolAddress((void**)&p_ah, d_ah);
    cudaGetSymbolAddress((void**)&p_al, d_al);
    cudaGetSymbolAddress((void**)&p_hh, d_hh);
    cudaGetSymbolAddress((void**)&p_hl, d_hl);
    cudaGetSymbolAddress((void**)&p_wh, d_wh);
    cudaGetSymbolAddress((void**)&p_wl, d_wl);

    {
        size_t n = (size_t)M_ * C_;
        ref_kernel<<<(Q_ + 255) / 256, 256>>>();
        bias_pack_kernel<<<(NLAYERS_ * 384 + 255) / 256, 256>>>(bsamp, battn);
        init_kernel<<<(unsigned)((n + 255) / 256), 256>>>(src, posf, lemb, x);
        wsplit_kernel<<<dim3(32, 32, 36), dim3(32, 8)>>>(Wval, Wsamp, Wattn,
                                                         Wout, Wfc1, Wfc2);
    }

    const dim3 gN256(2, M_ / 128);
    const dim3 gN384(3, M_ / 128);
    const dim3 gN1024(8, M_ / 128);
    const dim3 gLN(1, M_ / 128);

    for (int i = 0; i < NLAYERS_; i++) {
        const size_t wb = (size_t)i * W_LAYER;

        // value = x @ Wv + bv
        hgemm_kernel<false, true, false><<<gN256, 256, SMEM_DYN>>>(
            p_xh, p_xl, p_wh + wb + OFF_WV, p_wl + wb + OFF_WV,
            bval + i * C_, p_val, nullptr, nullptr, M_, 256, 256);
        // [off | logits] = q @ [Ws ; Wa] + [bs ; ba]
        hgemm_kernel<false, true, false><<<gN384, 256, SMEM_DYN>>>(
            p_qh, p_ql, p_wh + wb + OFF_WSA, p_wl + wb + OFF_WSA,
            p_bsa + i * 384, p_ol, nullptr, nullptr, M_, 384, 256);
        // deformable sampling -> (ah, al)
        deform_kernel<<<M_, 256>>>(p_val, p_ol);
        // x = LN(x + samp @ Wo + bo)   [fused]
        hgemm_ln_kernel<false><<<gLN, 512, SMEM_DYN2>>>(
            p_ah, p_al, p_wh + wb + OFF_WO, p_wl + wb + OFF_WO,
            bout + i * C_, g1 + i * C_, b1 + i * C_, x, 256);
        // hid = relu(x @ W1 + b1) -> split halves
        hgemm_kernel<true, false, true><<<gN1024, 256, SMEM_DYN>>>(
            p_xh, p_xl, p_wh + wb + OFF_W1, p_wl + wb + OFF_W1,
            bfc1 + i * FFN_, nullptr, p_hh, p_hl, M_, 1024, 256);
        // x = LN(x + hid @ W2 + b2)   [fused, also writes q splits]
        hgemm_ln_kernel<true><<<gLN, 512, SMEM_DYN2>>>(
            p_hh, p_hl, p_wh + wb + OFF_W2, p_wl + wb + OFF_W2,
            bfc2 + i * C_, g2 + i * C_, b2 + i * C_, x, 1024);
    }
}